// round 13
// baseline (speedup 1.0000x reference)
#include <cuda_runtime.h>
#include <math.h>

#define IMG_H 512
#define IMG_W 512
#define BATCH 16
#define TILE  32
#define HALO  3
#define RAW   38                 // TILE + 2*HALO
#define RAWP  39                 // odd pitch -> conflict-free strided column access
#define NTHREADS 256
#define GX (IMG_W / TILE)        // 16
#define GY (IMG_H / TILE)        // 16
#define NBLOCKS (BATCH * GX * GY)  // 4096
#define CHSTRIDE (IMG_H * IMG_W)
#define INV_N    (1.0f / 147.0f) // C*K*K
#define EPS      1e-8f
#define INV_TOTAL (1.0f / 4194304.0f)  // 1/(B*H*W)

__device__ float        g_partials[NBLOCKS];
__device__ unsigned int g_count = 0;

__global__ __launch_bounds__(NTHREADS)
void distloss_kernel(const float* __restrict__ pred,
                     const float* __restrict__ tgt,
                     float* __restrict__ out)
{
    // raw[0]=pred y, raw[1]=pred y2, raw[2]=tgt y, raw[3]=tgt y2
    // After Phase B, cols 0..31 of each row hold the horizontal 7-tap sums (in-place).
    __shared__ float raw[4][RAW * RAWP];
    __shared__ float red[8];
    __shared__ bool  isLast;

    const int tid   = threadIdx.x;
    const int b     = blockIdx.z;
    const int baseH = blockIdx.y * TILE;
    const int baseW = blockIdx.x * TILE;

    const float* pB = pred + (size_t)b * 3 * CHSTRIDE;
    const float* tB = tgt  + (size_t)b * 3 * CHSTRIDE;

    const bool interior =
        (baseH >= HALO) && (baseH + TILE + HALO <= IMG_H) &&
        (baseW >= HALO) && (baseW + TILE + HALO <= IMG_W);

    // ---- Phase A: load halo tiles for BOTH images, fold channels (y, y^2)
    if (interior) {
        // Aligned 40-float window [baseW-4, baseW+36): 10 float4 per row.
        // Window position of float j in quad q: col = 4q - 1 + j  (discard col<0, col>37)
        const float4* p0 = (const float4*)(pB + (baseH - HALO) * IMG_W + (baseW - 4));
        const float4* t0 = (const float4*)(tB + (baseH - HALO) * IMG_W + (baseW - 4));
        const int Q4 = CHSTRIDE / 4;          // channel stride in float4
        const int R4 = IMG_W / 4;             // row stride in float4
        #pragma unroll
        for (int k = 0; k < 2; k++) {
            int i = tid + k * NTHREADS;       // 380 items: (r, q)
            if (i < RAW * 10) {
                int r = i / 10, q = i - r * 10;
                const float4* pp = p0 + r * R4 + q;
                const float4* tp = t0 + r * R4 + q;
                float4 a0 = __ldg(pp);
                float4 a1 = __ldg(pp + Q4);
                float4 a2 = __ldg(pp + 2 * Q4);
                float4 b0 = __ldg(tp);
                float4 b1 = __ldg(tp + Q4);
                float4 b2 = __ldg(tp + 2 * Q4);
                float ya[4]  = {a0.x + a1.x + a2.x, a0.y + a1.y + a2.y,
                                a0.z + a1.z + a2.z, a0.w + a1.w + a2.w};
                float y2a[4] = {a0.x*a0.x + a1.x*a1.x + a2.x*a2.x,
                                a0.y*a0.y + a1.y*a1.y + a2.y*a2.y,
                                a0.z*a0.z + a1.z*a1.z + a2.z*a2.z,
                                a0.w*a0.w + a1.w*a1.w + a2.w*a2.w};
                float yb[4]  = {b0.x + b1.x + b2.x, b0.y + b1.y + b2.y,
                                b0.z + b1.z + b2.z, b0.w + b1.w + b2.w};
                float y2b[4] = {b0.x*b0.x + b1.x*b1.x + b2.x*b2.x,
                                b0.y*b0.y + b1.y*b1.y + b2.y*b2.y,
                                b0.z*b0.z + b1.z*b1.z + b2.z*b2.z,
                                b0.w*b0.w + b1.w*b1.w + b2.w*b2.w};
                int base = r * RAWP + 4 * q - 1;
                #pragma unroll
                for (int j = 0; j < 4; j++) {
                    int col = 4 * q - 1 + j;
                    if ((unsigned)col < (unsigned)RAW) {
                        raw[0][base + j] = ya[j];
                        raw[1][base + j] = y2a[j];
                        raw[2][base + j] = yb[j];
                        raw[3][base + j] = y2b[j];
                    }
                }
            }
        }
    } else {
        #pragma unroll
        for (int k = 0; k < 6; k++) {
            int i = tid + k * NTHREADS;
            if (i < RAW * RAW) {
                int r = i / RAW, c = i - r * RAW;
                int gh = baseH + r - HALO, gw = baseW + c - HALO;
                float a0 = 0.f, a1 = 0.f, a2 = 0.f;
                float b0 = 0.f, b1 = 0.f, b2 = 0.f;
                if ((unsigned)gh < (unsigned)IMG_H && (unsigned)gw < (unsigned)IMG_W) {
                    int off = gh * IMG_W + gw;
                    a0 = __ldg(pB + off);
                    a1 = __ldg(pB + off + CHSTRIDE);
                    a2 = __ldg(pB + off + 2 * CHSTRIDE);
                    b0 = __ldg(tB + off);
                    b1 = __ldg(tB + off + CHSTRIDE);
                    b2 = __ldg(tB + off + 2 * CHSTRIDE);
                }
                int s = r * RAWP + c;
                raw[0][s] = a0 + a1 + a2;
                raw[1][s] = a0 * a0 + a1 * a1 + a2 * a2;
                raw[2][s] = b0 + b1 + b2;
                raw[3][s] = b0 * b0 + b1 * b1 + b2 * b2;
            }
        }
    }
    __syncthreads();

    // ---- Phase B: horizontal 7-tap running sums, in-place (1-step delayed write).
    // 7-deep register ring: each of the 38 raw values is loaded exactly once.
    if (tid < 4 * RAW) {
        int which = tid / RAW;
        int r     = tid - which * RAW;
        float* row = &raw[which][r * RAWP];
        float buf[7];
        float run = 0.f;
        #pragma unroll
        for (int k = 0; k < 7; k++) { buf[k] = row[k]; run += buf[k]; }
        float hprev = run;
        #pragma unroll
        for (int c = 1; c < TILE; c++) {
            float add = row[c + 6];
            run += add - buf[(c - 1) % 7];
            row[c - 1] = hprev;          // col c-1 already consumed (read at step c-7)
            buf[(c - 1) % 7] = add;      // ring slot now holds col c+6
            hprev = run;
        }
        row[TILE - 1] = hprev;
    }
    __syncthreads();

    // ---- Phase C: vertical 7-tap running sums + std + smooth-L1
    const int c  = tid & 31;
    const int r0 = (tid >> 5) * 4;

    float sp[4];
    {
        float s = 0.f, s2 = 0.f, sub[3], sub2[3];
        #pragma unroll
        for (int k = 0; k < 7; k++) {
            float a = raw[0][(r0 + k) * RAWP + c];
            float q = raw[1][(r0 + k) * RAWP + c];
            if (k < 3) { sub[k] = a; sub2[k] = q; }
            s += a; s2 += q;
        }
        #pragma unroll
        for (int j = 0; j < 4; j++) {
            float mu  = s * INV_N;
            float var = s2 * INV_N - mu * mu;
            sp[j] = sqrtf(var + EPS);
            if (j < 3) {
                s  += raw[0][(r0 + j + 7) * RAWP + c] - sub[j];
                s2 += raw[1][(r0 + j + 7) * RAWP + c] - sub2[j];
            }
        }
    }
    float local = 0.f;
    {
        float s = 0.f, s2 = 0.f, sub[3], sub2[3];
        #pragma unroll
        for (int k = 0; k < 7; k++) {
            float a = raw[2][(r0 + k) * RAWP + c];
            float q = raw[3][(r0 + k) * RAWP + c];
            if (k < 3) { sub[k] = a; sub2[k] = q; }
            s += a; s2 += q;
        }
        #pragma unroll
        for (int j = 0; j < 4; j++) {
            float mu  = s * INV_N;
            float var = s2 * INV_N - mu * mu;
            float st  = sqrtf(var + EPS);
            float d   = sp[j] - st;
            float ad  = fabsf(d);
            local += (ad < 1.f) ? 0.5f * d * d : (ad - 0.5f);
            if (j < 3) {
                s  += raw[2][(r0 + j + 7) * RAWP + c] - sub[j];
                s2 += raw[3][(r0 + j + 7) * RAWP + c] - sub2[j];
            }
        }
    }

    // ---- Block reduction
    #pragma unroll
    for (int off = 16; off > 0; off >>= 1)
        local += __shfl_down_sync(0xFFFFFFFFu, local, off);
    if ((tid & 31) == 0) red[tid >> 5] = local;
    __syncthreads();

    if (tid == 0) {
        float bs = 0.f;
        #pragma unroll
        for (int w = 0; w < 8; w++) bs += red[w];
        int bidx = (blockIdx.z * GY + blockIdx.y) * GX + blockIdx.x;
        g_partials[bidx] = bs;
        __threadfence();
        unsigned old = atomicAdd(&g_count, 1u);
        isLast = (old == NBLOCKS - 1);
    }
    __syncthreads();

    // ---- Last block: deterministic final sum (fixed order), reset counter
    if (isLast) {
        float s = 0.f;
        for (int i = tid; i < NBLOCKS; i += NTHREADS)
            s += __ldcg(&g_partials[i]);
        #pragma unroll
        for (int off = 16; off > 0; off >>= 1)
            s += __shfl_down_sync(0xFFFFFFFFu, s, off);
        if ((tid & 31) == 0) red[tid >> 5] = s;
        __syncthreads();
        if (tid == 0) {
            float tot = 0.f;
            #pragma unroll
            for (int w = 0; w < 8; w++) tot += red[w];
            out[0] = tot * INV_TOTAL;
            g_count = 0;  // ready for next graph replay
        }
    }
}

extern "C" void kernel_launch(void* const* d_in, const int* in_sizes, int n_in,
                              void* d_out, int out_size)
{
    const float* pred = (const float*)d_in[0];  // pred_moire
    const float* tgt  = (const float*)d_in[1];  // moire
    dim3 grid(GX, GY, BATCH);                   // 4096 blocks
    distloss_kernel<<<grid, NTHREADS>>>(pred, tgt, (float*)d_out);
}

// round 17
// speedup vs baseline: 1.0525x; 1.0525x over previous
#include <cuda_runtime.h>
#include <cuda_fp16.h>
#include <math.h>

#define IMG_H 512
#define IMG_W 512
#define BATCH 16
#define TILE  32
#define HALO  3
#define RAW   38                 // TILE + 2*HALO
#define RAWP  39                 // odd pitch -> conflict-free access (4B half2 words)
#define HP    33                 // h-sum pitch (odd)
#define NTHREADS 256
#define GX (IMG_W / TILE)        // 16
#define GY (IMG_H / TILE)        // 16
#define NBLOCKS (BATCH * GX * GY)  // 4096
#define CHSTRIDE (IMG_H * IMG_W)
#define INV_N    (1.0f / 147.0f) // C*K*K
#define EPS      1e-8f
#define INV_TOTAL (1.0f / 4194304.0f)  // 1/(B*H*W)

__device__ float        g_partials[NBLOCKS];
__device__ unsigned int g_count = 0;

__global__ __launch_bounds__(NTHREADS)
void distloss_kernel(const float* __restrict__ pred,
                     const float* __restrict__ tgt,
                     float* __restrict__ out)
{
    // Packed (y, y2) tiles per image, fp16x2. raw: halo tile; hs: horizontal 7-tap sums.
    __shared__ __half2 raw[2][RAW * RAWP];
    __shared__ __half2 hs [2][RAW * HP];
    __shared__ float   red[8];
    __shared__ bool    isLast;

    const int tid   = threadIdx.x;
    const int b     = blockIdx.z;
    const int baseH = blockIdx.y * TILE;
    const int baseW = blockIdx.x * TILE;

    const float* pB = pred + (size_t)b * 3 * CHSTRIDE;
    const float* tB = tgt  + (size_t)b * 3 * CHSTRIDE;

    const bool interior =
        (baseH >= HALO) && (baseH + TILE + HALO <= IMG_H) &&
        (baseW >= HALO) && (baseW + TILE + HALO <= IMG_W);

    // ---- Phase A: load halo tiles for BOTH images, fold channels, pack (y,y2) fp16x2
    if (interior) {
        const float* p0 = pB + (baseH - HALO) * IMG_W + (baseW - HALO);
        const float* t0 = tB + (baseH - HALO) * IMG_W + (baseW - HALO);
        #pragma unroll
        for (int k = 0; k < 6; k++) {
            int i = tid + k * NTHREADS;
            if (i < RAW * RAW) {
                int r = i / RAW, c = i - r * RAW;
                int off = r * IMG_W + c;
                float a0 = __ldg(p0 + off);
                float a1 = __ldg(p0 + off + CHSTRIDE);
                float a2 = __ldg(p0 + off + 2 * CHSTRIDE);
                float b0 = __ldg(t0 + off);
                float b1 = __ldg(t0 + off + CHSTRIDE);
                float b2 = __ldg(t0 + off + 2 * CHSTRIDE);
                int s = r * RAWP + c;
                raw[0][s] = __floats2half2_rn(a0 + a1 + a2,
                                              a0*a0 + a1*a1 + a2*a2);
                raw[1][s] = __floats2half2_rn(b0 + b1 + b2,
                                              b0*b0 + b1*b1 + b2*b2);
            }
        }
    } else {
        #pragma unroll
        for (int k = 0; k < 6; k++) {
            int i = tid + k * NTHREADS;
            if (i < RAW * RAW) {
                int r = i / RAW, c = i - r * RAW;
                int gh = baseH + r - HALO, gw = baseW + c - HALO;
                float a0 = 0.f, a1 = 0.f, a2 = 0.f;
                float b0 = 0.f, b1 = 0.f, b2 = 0.f;
                if ((unsigned)gh < (unsigned)IMG_H && (unsigned)gw < (unsigned)IMG_W) {
                    int off = gh * IMG_W + gw;
                    a0 = __ldg(pB + off);
                    a1 = __ldg(pB + off + CHSTRIDE);
                    a2 = __ldg(pB + off + 2 * CHSTRIDE);
                    b0 = __ldg(tB + off);
                    b1 = __ldg(tB + off + CHSTRIDE);
                    b2 = __ldg(tB + off + 2 * CHSTRIDE);
                }
                int s = r * RAWP + c;
                raw[0][s] = __floats2half2_rn(a0 + a1 + a2,
                                              a0*a0 + a1*a1 + a2*a2);
                raw[1][s] = __floats2half2_rn(b0 + b1 + b2,
                                              b0*b0 + b1*b1 + b2*b2);
            }
        }
    }
    __syncthreads();

    // ---- Phase B: horizontal 7-tap running sums (fp32 accum), packed loads/stores.
    // 152 tasks: (img, row, half) — each covers 16 output cols. Separate dst arrays.
    if (tid < 2 * RAW * 2) {
        int img  = tid / (2 * RAW);
        int rem  = tid - img * (2 * RAW);
        int row  = rem >> 1;
        int half = rem & 1;
        int c0   = half * 16;
        const __half2* src = &raw[img][row * RAWP + c0];
        __half2*       dst = &hs [img][row * HP   + c0];

        float2 ring[7];
        float sy = 0.f, sy2 = 0.f;
        #pragma unroll
        for (int k = 0; k < 7; k++) {
            float2 v = __half22float2(src[k]);
            ring[k] = v; sy += v.x; sy2 += v.y;
        }
        dst[0] = __floats2half2_rn(sy, sy2);
        #pragma unroll
        for (int i = 1; i < 16; i++) {
            float2 v = __half22float2(src[6 + i]);
            sy  += v.x - ring[(i - 1) % 7].x;
            sy2 += v.y - ring[(i - 1) % 7].y;
            ring[(i - 1) % 7] = v;
            dst[i] = __floats2half2_rn(sy, sy2);
        }
    }
    __syncthreads();

    // ---- Phase C: vertical 7-tap running sums + std + smooth-L1 (packed loads)
    const int c  = tid & 31;
    const int r0 = (tid >> 5) * 4;

    float sp[4];
    {
        float s = 0.f, s2 = 0.f; float2 sub[3];
        #pragma unroll
        for (int k = 0; k < 7; k++) {
            float2 v = __half22float2(hs[0][(r0 + k) * HP + c]);
            if (k < 3) sub[k] = v;
            s += v.x; s2 += v.y;
        }
        #pragma unroll
        for (int j = 0; j < 4; j++) {
            float mu  = s * INV_N;
            float var = s2 * INV_N - mu * mu;
            sp[j] = sqrtf(var + EPS);
            if (j < 3) {
                float2 v = __half22float2(hs[0][(r0 + j + 7) * HP + c]);
                s += v.x - sub[j].x; s2 += v.y - sub[j].y;
            }
        }
    }
    float local = 0.f;
    {
        float s = 0.f, s2 = 0.f; float2 sub[3];
        #pragma unroll
        for (int k = 0; k < 7; k++) {
            float2 v = __half22float2(hs[1][(r0 + k) * HP + c]);
            if (k < 3) sub[k] = v;
            s += v.x; s2 += v.y;
        }
        #pragma unroll
        for (int j = 0; j < 4; j++) {
            float mu  = s * INV_N;
            float var = s2 * INV_N - mu * mu;
            float st  = sqrtf(var + EPS);
            float d   = sp[j] - st;
            float ad  = fabsf(d);
            local += (ad < 1.f) ? 0.5f * d * d : (ad - 0.5f);
            if (j < 3) {
                float2 v = __half22float2(hs[1][(r0 + j + 7) * HP + c]);
                s += v.x - sub[j].x; s2 += v.y - sub[j].y;
            }
        }
    }

    // ---- Block reduction
    #pragma unroll
    for (int off = 16; off > 0; off >>= 1)
        local += __shfl_down_sync(0xFFFFFFFFu, local, off);
    if ((tid & 31) == 0) red[tid >> 5] = local;
    __syncthreads();

    if (tid == 0) {
        float bs = 0.f;
        #pragma unroll
        for (int w = 0; w < 8; w++) bs += red[w];
        int bidx = (blockIdx.z * GY + blockIdx.y) * GX + blockIdx.x;
        g_partials[bidx] = bs;
        __threadfence();
        unsigned old = atomicAdd(&g_count, 1u);
        isLast = (old == NBLOCKS - 1);
    }
    __syncthreads();

    // ---- Last block: deterministic final sum (fixed order), reset counter
    if (isLast) {
        float s = 0.f;
        for (int i = tid; i < NBLOCKS; i += NTHREADS)
            s += __ldcg(&g_partials[i]);
        #pragma unroll
        for (int off = 16; off > 0; off >>= 1)
            s += __shfl_down_sync(0xFFFFFFFFu, s, off);
        if ((tid & 31) == 0) red[tid >> 5] = s;
        __syncthreads();
        if (tid == 0) {
            float tot = 0.f;
            #pragma unroll
            for (int w = 0; w < 8; w++) tot += red[w];
            out[0] = tot * INV_TOTAL;
            g_count = 0;  // ready for next graph replay
        }
    }
}

extern "C" void kernel_launch(void* const* d_in, const int* in_sizes, int n_in,
                              void* d_out, int out_size)
{
    const float* pred = (const float*)d_in[0];  // pred_moire
    const float* tgt  = (const float*)d_in[1];  // moire
    dim3 grid(GX, GY, BATCH);                   // 4096 blocks
    distloss_kernel<<<grid, NTHREADS>>>(pred, tgt, (float*)d_out);
}